// round 12
// baseline (speedup 1.0000x reference)
#include <cuda_runtime.h>
#include <math.h>

#define TN     512
#define TRANGE 8.0f                              // table covers x0 in [-8, 8)
#define TSCALE ((float)TN / (2.0f * TRANGE))     // 32
#define TOFFS  ((float)(TN / 2))                 // 256

#define RPC    256                               // rows per chunk (= blockDim)
#define F4PC   (RPC * 18 / 4)                    // float4 per chunk = 1152
#define XWORDS (RPC * 19)                        // pitch-19 staging (4864 words)

// Constant weights (prescaled): [0:4) w_ih' [4:8) w_hh' [8:12) bias'
// (i,f,o gates scaled by 0.5 to fold into sigmoid; g unscaled)
// [12:30) w_lin  [30] b_lin
__constant__ float c_w[31];

__device__ float  g_stage[31];
__device__ float4 g_tab[TN];   // (h0, c0, dh, dc) as function of x0

__device__ __forceinline__ float tanh_fast(float x) {
    float y;
    asm("tanh.approx.f32 %0, %1;" : "=f"(y) : "f"(x));
    return y;
}
// argument already prescaled by 0.5
__device__ __forceinline__ float sigmoid_pre(float half_x) {
    return fmaf(tanh_fast(half_x), 0.5f, 0.5f);
}

// ---------------- setup: stage weights + build exact step0 table -----------
__device__ __forceinline__ void step0_exact(
    float x, float wi, float wg, float wo, float bi, float bg, float bo,
    float* h0, float* c0)
{
    float i0 = 1.0f / (1.0f + expf(-(fmaf(wi, x, bi))));
    float g0 = tanhf(fmaf(wg, x, bg));
    float o0 = 1.0f / (1.0f + expf(-(fmaf(wo, x, bo))));
    float c  = i0 * g0;
    *c0 = c;
    *h0 = o0 * tanhf(c);
}

__global__ void setup_kernel(const float* __restrict__ w_ih,
                             const float* __restrict__ w_hh,
                             const float* __restrict__ b_ih,
                             const float* __restrict__ b_hh,
                             const float* __restrict__ w_lin,
                             const float* __restrict__ b_lin)
{
    int t = threadIdx.x;
    if (t < 4) {
        float s = (t == 2) ? 1.0f : 0.5f;       // g gate unscaled
        g_stage[t]     = w_ih[t] * s;
        g_stage[4 + t] = w_hh[t] * s;
        g_stage[8 + t] = (b_ih[t] + b_hh[t]) * s;
    } else if (t < 22) {
        g_stage[8 + t] = w_lin[t - 4];          // 12..29
    } else if (t == 22) {
        g_stage[30] = b_lin[0];
    }

    const float wi = w_ih[0], wg = w_ih[2], wo = w_ih[3];
    const float bi = b_ih[0] + b_hh[0];
    const float bg = b_ih[2] + b_hh[2];
    const float bo = b_ih[3] + b_hh[3];
    const float inv = 1.0f / TSCALE;

    for (int i = t; i < TN; i += blockDim.x) {
        float x0 = ((float)i       - TOFFS) * inv;
        float x1 = ((float)(i + 1) - TOFFS) * inv;
        float h0, c0, h1, c1;
        step0_exact(x0, wi, wg, wo, bi, bg, bo, &h0, &c0);
        step0_exact(x1, wi, wg, wo, bi, bg, bo, &h1, &c1);
        g_tab[i] = make_float4(h0, c0, h1 - h0, c1 - c0);
    }
}

// Steps 1-2 of one element given (h,c) from the step-0 gather.
#define STEPS12(ACC, HC, X1, X2, WI)                                          \
    do {                                                                      \
        float h_ = (HC).x, c_ = (HC).y;                                       \
        ACC = fmaf(h_, c_w[(WI)], ACC);                                       \
        float i1_ = sigmoid_pre(fmaf(c_w[4], h_, fmaf(c_w[0], (X1), c_w[8])));\
        float f1_ = sigmoid_pre(fmaf(c_w[5], h_, fmaf(c_w[1], (X1), c_w[9])));\
        float g1_ = tanh_fast  (fmaf(c_w[6], h_, fmaf(c_w[2], (X1), c_w[10])));\
        float o1_ = sigmoid_pre(fmaf(c_w[7], h_, fmaf(c_w[3], (X1), c_w[11])));\
        c_ = fmaf(f1_, c_, i1_ * g1_);                                        \
        h_ = o1_ * tanh_fast(c_);                                             \
        ACC = fmaf(h_, c_w[(WI) + 1], ACC);                                   \
        float i2_ = sigmoid_pre(fmaf(c_w[4], h_, fmaf(c_w[0], (X2), c_w[8])));\
        float f2_ = sigmoid_pre(fmaf(c_w[5], h_, fmaf(c_w[1], (X2), c_w[9])));\
        float g2_ = tanh_fast  (fmaf(c_w[6], h_, fmaf(c_w[2], (X2), c_w[10])));\
        float o2_ = sigmoid_pre(fmaf(c_w[7], h_, fmaf(c_w[3], (X2), c_w[11])));\
        c_ = fmaf(f2_, c_, i2_ * g2_);                                        \
        h_ = o2_ * tanh_fast(c_);                                             \
        ACC = fmaf(h_, c_w[(WI) + 2], ACC);                                   \
    } while (0)

// step-0 table gather: (h0, c0) as float2, from x0 only
__device__ __forceinline__ float2 step0_gather(float x0, const float4* __restrict__ stab) {
    float t = fmaf(x0, TSCALE, TOFFS);
    t = fminf(fmaxf(t, 0.0f), (float)TN - 0.51f);
    int   i  = (int)t;
    float dx = t - (float)i;
    float4 e = stab[i];
    return make_float2(fmaf(dx, e.z, e.x), fmaf(dx, e.w, e.y));
}

// ---------------- main kernel: one 256-row chunk per CTA, pitch-19 smem ----
__global__ __launch_bounds__(256) void lstm_lin_kernel(
    const float* __restrict__ x, float* __restrict__ out)
{
    __shared__ float4 stab[TN];          // 8 KB step-0 table
    __shared__ float  xs[XWORDS];        // 19 KB input chunk, pitch-19 rows

    const int tid = threadIdx.x;

    // table fill (coalesced, L2-hot)
    stab[tid]       = __ldg(&g_tab[tid]);
    stab[tid + 256] = __ldg(&g_tab[tid + 256]);

    // chunk load: coalesced float4 LDG, pitch-19 scatter (p = f + f/18)
    {
        const float4* src = reinterpret_cast<const float4*>(x)
                          + (size_t)blockIdx.x * F4PC;
#pragma unroll
        for (int k = 0; k < 5; k++) {
            int i = tid + 256 * k;
            if (k < 4 || i < F4PC) {            // FIXED: i already includes +1024
                float4 d = __ldg(src + i);
                int f = 4 * i;
                float vv[4] = {d.x, d.y, d.z, d.w};
#pragma unroll
                for (int j = 0; j < 4; j++) {
                    int fj = f + j;
                    int rj = (int)(((unsigned)fj * 58255u) >> 20);  // fj / 18
                    xs[fj + rj] = vv[j];
                }
            }
        }
    }
    __syncthreads();

    // compute: thread tid owns row tid (pitch 19 -> conflict-free LDS)
    const float* row = xs + tid * 19;

    // hoist all 6 step-0 gathers (index depends only on x0 = row[3e])
    float2 hc0 = step0_gather(row[ 0], stab);
    float2 hc1 = step0_gather(row[ 3], stab);
    float2 hc2 = step0_gather(row[ 6], stab);
    float2 hc3 = step0_gather(row[ 9], stab);
    float2 hc4 = step0_gather(row[12], stab);
    float2 hc5 = step0_gather(row[15], stab);

    float acc = c_w[30];
    STEPS12(acc, hc0, row[ 1], row[ 2], 12);
    STEPS12(acc, hc1, row[ 4], row[ 5], 15);
    STEPS12(acc, hc2, row[ 7], row[ 8], 18);
    STEPS12(acc, hc3, row[10], row[11], 21);
    STEPS12(acc, hc4, row[13], row[14], 24);
    STEPS12(acc, hc5, row[16], row[17], 27);

    out[blockIdx.x * RPC + tid] = acc;
}

extern "C" void kernel_launch(void* const* d_in, const int* in_sizes, int n_in,
                              void* d_out, int out_size)
{
    // Inputs: x, w_ih, w_hh, b_ih, b_hh, w_lin, b_lin
    const float* x = (const float*)d_in[0];

    setup_kernel<<<1, 256>>>((const float*)d_in[1], (const float*)d_in[2],
                             (const float*)d_in[3], (const float*)d_in[4],
                             (const float*)d_in[5], (const float*)d_in[6]);

    void* stage_ptr = nullptr;
    cudaGetSymbolAddress(&stage_ptr, g_stage);
    cudaMemcpyToSymbolAsync(c_w, stage_ptr, 31 * sizeof(float), 0,
                            cudaMemcpyDeviceToDevice, 0);

    int nchunks = out_size / RPC;   // 8192 CTAs, one chunk each
    lstm_lin_kernel<<<nchunks, 256>>>(x, (float*)d_out);
}